// round 6
// baseline (speedup 1.0000x reference)
#include <cuda_runtime.h>
#include <cuda_fp16.h>
#include <cstdint>

// ============================================================================
// LSTMCell on GB300 via mma.sync (HMMA) — tcgen05 unavailable (compute_103 PTX).
// gates[B,512] = [x|h] @ Wcat^T, fp16 operands / fp32 accum, fused epilogue.
// Persistent weight-stationary CTAs: CTA owns (qh quarter of 32 hcols x 4 gates),
// loops over batch tiles of 128 rows.
// ============================================================================

// Weights pre-packed in mma-fragment-ready layout:
// g_wb[qh][ ((ks*16 + nt)*32 + lane)*8 + j*4 ] : 2 fp16 (b0/b1 halves of B frag)
//   ks = k/16 (16), nt = q*4 + t (16), lane = (n%8)*4 + ((k%8)>>1), j = (k%16)>=8
__device__ __align__(16) unsigned char g_wb[4][65536];

__device__ __forceinline__ uint32_t smem_u32(const void* p) {
    uint32_t a;
    asm("{ .reg .u64 t; cvta.to.shared.u64 t, %1; cvt.u32.u64 %0, t; }"
        : "=r"(a) : "l"(p));
    return a;
}

__device__ __forceinline__ float fast_sigmoid(float x) {
    float e, r;
    asm("ex2.approx.f32 %0, %1;" : "=f"(e) : "f"(-1.4426950408889634f * x));
    asm("rcp.approx.f32 %0, %1;" : "=f"(r) : "f"(1.0f + e));
    return r;
}
__device__ __forceinline__ float fast_tanh(float x) {
    float e, r;
    asm("ex2.approx.f32 %0, %1;" : "=f"(e) : "f"(2.8853900817779268f * x));
    asm("rcp.approx.f32 %0, %1;" : "=f"(r) : "f"(e + 1.0f));
    return 1.0f - 2.0f * r;   // handles +-inf correctly -> +-1
}

__device__ __forceinline__ void mma16816(float* d, const uint32_t* a,
                                         uint32_t b0, uint32_t b1) {
    asm volatile(
        "mma.sync.aligned.m16n8k16.row.col.f32.f16.f16.f32 "
        "{%0,%1,%2,%3}, {%4,%5,%6,%7}, {%8,%9}, {%0,%1,%2,%3};\n"
        : "+f"(d[0]), "+f"(d[1]), "+f"(d[2]), "+f"(d[3])
        : "r"(a[0]), "r"(a[1]), "r"(a[2]), "r"(a[3]), "r"(b0), "r"(b1));
}

// ---------------- SMEM layout (dynamic) ----------------
// [0, 65536)          : W fragments (16 ks x 16 nt x 32 lane x 8B)
// [65536, 65536+16384): A ring, 2 slots x (2 ks2 x 8 mtile x 32 lane x 16B)
// [81920, 82432)      : bias bs[4][32]
static constexpr int SMEM_W  = 0;
static constexpr int SMEM_A  = 65536;
static constexpr int SMEM_BS = 65536 + 16384;
static constexpr int SMEM_TOTAL = SMEM_BS + 512;

// ============================================================================
// Kernel 1: pack weights fp32 -> fp16 B-fragment layout in g_wb.
// ============================================================================
__global__ void wconv_kernel(
    const float* __restrict__ Wii, const float* __restrict__ Whi,
    const float* __restrict__ Wif, const float* __restrict__ Whf,
    const float* __restrict__ Wig, const float* __restrict__ Whg,
    const float* __restrict__ Wio, const float* __restrict__ Who)
{
    int idx = blockIdx.x * 256 + threadIdx.x;   // 0..65535 (pairs)
    int gcol = idx >> 7;        // 0..511
    int kp   = idx & 127;       // pair index, k = 2*kp
    int k    = kp * 2;

    int q    = gcol >> 7;
    int hcol = gcol & 127;
    int qh   = hcol >> 5;
    int hc   = hcol & 31;

    int nt   = q * 4 + (hc >> 3);
    int lane = (hc & 7) * 4 + ((k & 7) >> 1);
    int ks   = k >> 4;
    int j    = (k >> 3) & 1;

    const float* Wx;
    const float* Wh;
    switch (q) {
        case 0:  Wx = Wii; Wh = Whi; break;
        case 1:  Wx = Wif; Wh = Whf; break;
        case 2:  Wx = Wig; Wh = Whg; break;
        default: Wx = Wio; Wh = Who; break;
    }
    float2 v;
    if (k < 128) v = ((const float2*)(Wx + hcol * 128))[kp];
    else         v = ((const float2*)(Wh + hcol * 128))[kp - 64];

    __half2 hv = __floats2half2_rn(v.x, v.y);
    *(uint32_t*)&g_wb[qh][(((ks * 16 + nt) * 32 + lane) * 8) + j * 4] =
        *(uint32_t*)&hv;
}

// ============================================================================
// Kernel 2: persistent GEMM + LSTM epilogue.
// grid = 296 CTAs x 256 threads. blk&3 = qh (hcol quarter), blk>>2 = tile base.
// Warp w: mgroup = w&3 (2 mtiles of 16 rows), g = w>>2 (nt half).
// ============================================================================
__global__ void __launch_bounds__(256, 2)
lstm_main_kernel(
    const float* __restrict__ x, const float* __restrict__ h_t,
    const float* __restrict__ c_t,
    const float* __restrict__ b_i, const float* __restrict__ b_f,
    const float* __restrict__ b_g, const float* __restrict__ b_o,
    float* __restrict__ out, int batch, int mt_total)
{
    extern __shared__ char smem[];
    const uint32_t sb = smem_u32(smem);
    const uint32_t sW = sb + SMEM_W;
    const uint32_t sA = sb + SMEM_A;
    float* bs = (float*)(smem + SMEM_BS);

    const int tid  = threadIdx.x;
    const int wid  = tid >> 5;
    const int lane = tid & 31;
    const int qh   = blockIdx.x & 3;
    const int cta  = blockIdx.x >> 2;          // 0..73
    const int mt_stride = gridDim.x >> 2;      // 74

    const int mgroup = wid & 3;
    const int g      = wid >> 2;

    // ---- load W fragments (once) via cp.async ----
    {
        const char* src = (const char*)&g_wb[qh][0] + tid * 16;
        uint32_t dst = sW + tid * 16;
        #pragma unroll
        for (int i = 0; i < 16; i++) {
            asm volatile("cp.async.ca.shared.global [%0], [%1], 16;\n"
                         :: "r"(dst + i * 4096), "l"(src + i * 4096));
        }
        asm volatile("cp.async.commit_group;\n" ::: "memory");
    }
    // ---- biases for this quarter: bs[q][hc] ----
    if (tid < 128) {
        int q  = tid >> 5;
        int hc = tid & 31;
        const float* bp = (q == 0) ? b_i : (q == 1) ? b_f : (q == 2) ? b_g : b_o;
        bs[tid] = bp[qh * 32 + hc];
    }
    asm volatile("cp.async.wait_group 0;\n" ::: "memory");
    __syncthreads();

    // A-loader thread mapping (fixed): rows (r, r+8), 8 cols per chunk
    const int cq8 = tid & 3;                   // 8-col group within 32-col chunk
    const int rp  = tid >> 2;                  // 0..63
    const int arow = ((rp >> 3) << 4) + (rp & 7);   // r in {0..7,16..23,...}
    const int mtl  = rp >> 3;                  // arow>>4
    const int ks2w = cq8 >> 1;                 // writer ks2
    const size_t cbase = (size_t)batch * 128;

    // ---- persistent tile loop ----
    for (int mt = cta; mt < mt_total; mt += mt_stride) {

        float acc[2][4][2][4];                 // [m2][gate][e][frag]
        #pragma unroll
        for (int a0 = 0; a0 < 2; a0++)
            #pragma unroll
            for (int a1 = 0; a1 < 4; a1++)
                #pragma unroll
                for (int a2 = 0; a2 < 2; a2++)
                    #pragma unroll
                    for (int a3 = 0; a3 < 4; a3++)
                        acc[a0][a1][a2][a3] = 0.0f;

        float4 u0, u1, v0, v1;                 // staging: rows arow, arow+8 x 8 cols

        // -- load a 32-col chunk's worth for this thread --
        auto LOAD_CHUNK = [&](int chunk) {
            int cb = chunk * 32 + cq8 * 8;
            const float* base = (cb < 128) ? x : h_t;
            int cc = cb & 127;
            const float* p0 = base + ((size_t)(mt * 128 + arow)) * 128 + cc;
            const float* p1 = p0 + (size_t)8 * 128;
            u0 = __ldg((const float4*)p0);
            u1 = __ldg((const float4*)(p0 + 4));
            v0 = __ldg((const float4*)p1);
            v1 = __ldg((const float4*)(p1 + 4));
        };
        // -- convert + store staged chunk into ring slot chunk&1 --
        auto STS_CHUNK = [&](int chunk) {
            int slot = chunk & 1;
            int ks   = chunk * 2 + ks2w;
            int swz  = (ks & 7) << 2;
            float ur[8] = {u0.x, u0.y, u0.z, u0.w, u1.x, u1.y, u1.z, u1.w};
            float vr[8] = {v0.x, v0.y, v0.z, v0.w, v1.x, v1.y, v1.z, v1.w};
            #pragma unroll
            for (int p = 0; p < 4; p++) {
                int lanep = ((arow & 7) << 2) + p;
                uint32_t addr = sA + slot * 8192
                              + (((ks2w << 3) + mtl) * 32 + (lanep ^ swz)) * 16
                              + ((cq8 & 1) << 3);
                __half2 lo = __floats2half2_rn(ur[2 * p], ur[2 * p + 1]);
                __half2 hi = __floats2half2_rn(vr[2 * p], vr[2 * p + 1]);
                asm volatile("st.shared.v2.b32 [%0], {%1, %2};\n"
                             :: "r"(addr), "r"(*(uint32_t*)&lo), "r"(*(uint32_t*)&hi));
            }
        };

        LOAD_CHUNK(0);
        STS_CHUNK(0);
        __syncthreads();

        #pragma unroll
        for (int chunk = 0; chunk < 8; chunk++) {
            if (chunk < 7) LOAD_CHUNK(chunk + 1);

            const int slot = chunk & 1;
            #pragma unroll
            for (int ks2 = 0; ks2 < 2; ks2++) {
                const int ks  = chunk * 2 + ks2;
                const int swz = (ks & 7) << 2;
                uint32_t afr[2][4];
                #pragma unroll
                for (int m2 = 0; m2 < 2; m2++) {
                    int mtile = (mgroup << 1) + m2;
                    uint32_t addr = sA + slot * 8192
                                  + (((ks2 << 3) + mtile) * 32 + (lane ^ swz)) * 16;
                    asm volatile("ld.shared.v4.b32 {%0,%1,%2,%3}, [%4];\n"
                                 : "=r"(afr[m2][0]), "=r"(afr[m2][1]),
                                   "=r"(afr[m2][2]), "=r"(afr[m2][3])
                                 : "r"(addr));
                }
                #pragma unroll
                for (int q = 0; q < 4; q++) {
                    #pragma unroll
                    for (int e = 0; e < 2; e++) {
                        int nt = q * 4 + g * 2 + e;
                        uint32_t baddr = sW + (((ks * 16 + nt) * 32 + lane) * 8);
                        uint32_t b0, b1;
                        asm volatile("ld.shared.v2.b32 {%0,%1}, [%2];\n"
                                     : "=r"(b0), "=r"(b1) : "r"(baddr));
                        mma16816(acc[0][q][e], afr[0], b0, b1);
                        mma16816(acc[1][q][e], afr[1], b0, b1);
                    }
                }
            }
            __syncthreads();
            if (chunk < 7) {
                STS_CHUNK(chunk + 1);
                __syncthreads();
            }
        }

        // ---- epilogue ----
        #pragma unroll
        for (int m2 = 0; m2 < 2; m2++) {
            const int r0 = mt * 128 + (mgroup << 5) + (m2 << 4) + (lane >> 2);
            #pragma unroll
            for (int e = 0; e < 2; e++) {
                const int hc32 = (((g << 1) + e) << 3) + ((lane & 3) << 1);
                const int hcol = (qh << 5) + hc32;
                const float bi0 = bs[hc32],      bi1 = bs[hc32 + 1];
                const float bf0 = bs[32 + hc32], bf1 = bs[32 + hc32 + 1];
                const float bg0 = bs[64 + hc32], bg1 = bs[64 + hc32 + 1];
                const float bo0 = bs[96 + hc32], bo1 = bs[96 + hc32 + 1];
                #pragma unroll
                for (int rh = 0; rh < 2; rh++) {
                    const int row = r0 + rh * 8;
                    const float2 cv =
                        __ldg((const float2*)(c_t + (size_t)row * 128 + hcol));

                    float ia0 = acc[m2][0][e][rh * 2 + 0] + bi0;
                    float ia1 = acc[m2][0][e][rh * 2 + 1] + bi1;
                    float fa0 = acc[m2][1][e][rh * 2 + 0] + bf0;
                    float fa1 = acc[m2][1][e][rh * 2 + 1] + bf1;
                    float ga0 = acc[m2][2][e][rh * 2 + 0] + bg0;
                    float ga1 = acc[m2][2][e][rh * 2 + 1] + bg1;
                    float oa0 = acc[m2][3][e][rh * 2 + 0] + bo0;
                    float oa1 = acc[m2][3][e][rh * 2 + 1] + bo1;

                    float it0 = fast_sigmoid(ia0), it1 = fast_sigmoid(ia1);
                    float ft0 = fast_sigmoid(fa0), ft1 = fast_sigmoid(fa1);
                    float gt0 = fast_tanh(ga0),    gt1 = fast_tanh(ga1);
                    float ot0 = fast_sigmoid(oa0), ot1 = fast_sigmoid(oa1);

                    float cn0 = ft0 * cv.x + it0 * gt0;
                    float cn1 = ft1 * cv.y + it1 * gt1;
                    float hn0 = ot0 * fast_tanh(cn0);
                    float hn1 = ot1 * fast_tanh(cn1);

                    float2 ho = make_float2(hn0, hn1);
                    float2 co = make_float2(cn0, cn1);
                    *(float2*)(out + (size_t)row * 128 + hcol) = ho;
                    *(float2*)(out + cbase + (size_t)row * 128 + hcol) = co;
                }
            }
        }
        __syncthreads();   // A ring reuse safety across tiles
    }
}

// ============================================================================
// Host launch
// ============================================================================
extern "C" void kernel_launch(void* const* d_in, const int* in_sizes, int n_in,
                              void* d_out, int out_size)
{
    (void)n_in; (void)out_size;
    const float* x   = (const float*)d_in[0];
    const float* h_t = (const float*)d_in[1];
    const float* c_t = (const float*)d_in[2];
    const float* Wii = (const float*)d_in[3];
    const float* Whi = (const float*)d_in[4];
    const float* b_i = (const float*)d_in[5];
    const float* Wif = (const float*)d_in[6];
    const float* Whf = (const float*)d_in[7];
    const float* b_f = (const float*)d_in[8];
    const float* Wig = (const float*)d_in[9];
    const float* Whg = (const float*)d_in[10];
    const float* b_g = (const float*)d_in[11];
    const float* Wio = (const float*)d_in[12];
    const float* Who = (const float*)d_in[13];
    const float* b_o = (const float*)d_in[14];

    const int batch    = in_sizes[0] / 128;
    const int mt_total = batch / 128;

    wconv_kernel<<<256, 256>>>(Wii, Whi, Wif, Whf, Wig, Whg, Wio, Who);

    static bool attr_set = false;
    if (!attr_set) {
        cudaFuncSetAttribute(lstm_main_kernel,
                             cudaFuncAttributeMaxDynamicSharedMemorySize,
                             SMEM_TOTAL);
        attr_set = true;
    }
    lstm_main_kernel<<<296, 256, SMEM_TOTAL>>>(
        x, h_t, c_t, b_i, b_f, b_g, b_o, (float*)d_out, batch, mt_total);
}

// round 7
// speedup vs baseline: 1.1542x; 1.1542x over previous
#include <cuda_runtime.h>
#include <cuda_fp16.h>
#include <cstdint>

// ============================================================================
// LSTMCell on GB300 via mma.sync (HMMA) — tcgen05 unavailable (compute_103 PTX).
// gates[B,512] = [x|h] @ Wcat^T, fp16 operands / fp32 accum, fused epilogue.
//
// R6 -> R7: A operand loaded FRAGMENT-DIRECT from gmem (LDG.128 -> cvt -> mma)
// using a k-permutation shared by A and B. No A smem ring, no STS/LDS for A,
// ZERO __syncthreads in the persistent tile loop. B fragments paired (e=0,1)
// so one LDS.128 feeds 4 HMMAs.
// ============================================================================

// Weights pre-packed in mma-fragment-ready layout with k-permutation pi:
//   within each 16-wide k-chunk: frag-pos {2l,2l+1}   <- actual k {4l,4l+1}
//                                frag-pos {2l+8,2l+9} <- actual k {4l+2,4l+3}
// addr = (((ks*8 + ntp)*32 + lane)*16) + e*8 + j*4
//   ks = k/16, ntp = q*2 + (t>>1), e = t&1 (t = hcol-8-group), j = (k>>1)&1,
//   lane = n8*4 + l  (n8 = n%8, l = (k>>2)&3)
__device__ __align__(16) unsigned char g_wb[4][65536];

__device__ __forceinline__ uint32_t smem_u32(const void* p) {
    uint32_t a;
    asm("{ .reg .u64 t; cvta.to.shared.u64 t, %1; cvt.u32.u64 %0, t; }"
        : "=r"(a) : "l"(p));
    return a;
}

__device__ __forceinline__ float fast_sigmoid(float x) {
    float e, r;
    asm("ex2.approx.f32 %0, %1;" : "=f"(e) : "f"(-1.4426950408889634f * x));
    asm("rcp.approx.f32 %0, %1;" : "=f"(r) : "f"(1.0f + e));
    return r;
}
__device__ __forceinline__ float fast_tanh(float x) {
    float e, r;
    asm("ex2.approx.f32 %0, %1;" : "=f"(e) : "f"(2.8853900817779268f * x));
    asm("rcp.approx.f32 %0, %1;" : "=f"(r) : "f"(e + 1.0f));
    return 1.0f - 2.0f * r;   // handles +-inf correctly -> +-1
}

__device__ __forceinline__ uint32_t cvt_h2(float lo, float hi) {
    uint32_t r;
    asm("cvt.rn.f16x2.f32 %0, %1, %2;" : "=r"(r) : "f"(hi), "f"(lo));
    return r;
}

__device__ __forceinline__ void mma16816(float* d, const uint32_t* a,
                                         uint32_t b0, uint32_t b1) {
    asm volatile(
        "mma.sync.aligned.m16n8k16.row.col.f32.f16.f16.f32 "
        "{%0,%1,%2,%3}, {%4,%5,%6,%7}, {%8,%9}, {%0,%1,%2,%3};\n"
        : "+f"(d[0]), "+f"(d[1]), "+f"(d[2]), "+f"(d[3])
        : "r"(a[0]), "r"(a[1]), "r"(a[2]), "r"(a[3]), "r"(b0), "r"(b1));
}

// ---------------- SMEM layout (dynamic) ----------------
// [0, 65536)      : W fragments
// [65536, 66048)  : bias bs[4][32]
static constexpr int SMEM_W  = 0;
static constexpr int SMEM_BS = 65536;
static constexpr int SMEM_TOTAL = SMEM_BS + 512;

// ============================================================================
// Kernel 1: pack weights fp32 -> fp16 B-fragment layout (with k-permutation).
// ============================================================================
__global__ void wconv_kernel(
    const float* __restrict__ Wii, const float* __restrict__ Whi,
    const float* __restrict__ Wif, const float* __restrict__ Whf,
    const float* __restrict__ Wig, const float* __restrict__ Whg,
    const float* __restrict__ Wio, const float* __restrict__ Who)
{
    int idx = blockIdx.x * 256 + threadIdx.x;   // 0..65535 (pairs)
    int gcol = idx >> 7;        // 0..511
    int kp   = idx & 127;       // pair index, k = 2*kp
    int k    = kp * 2;

    int q    = gcol >> 7;
    int hcol = gcol & 127;
    int qh   = hcol >> 5;
    int hc   = hcol & 31;

    int t    = hc >> 3;                 // 8-col group within 32
    int ntp  = q * 2 + (t >> 1);
    int e    = t & 1;
    int l    = (k >> 2) & 3;
    int j    = (k >> 1) & 1;
    int lane = (hc & 7) * 4 + l;
    int ks   = k >> 4;

    const float* Wx;
    const float* Wh;
    switch (q) {
        case 0:  Wx = Wii; Wh = Whi; break;
        case 1:  Wx = Wif; Wh = Whf; break;
        case 2:  Wx = Wig; Wh = Whg; break;
        default: Wx = Wio; Wh = Who; break;
    }
    float2 v;
    if (k < 128) v = ((const float2*)(Wx + hcol * 128))[kp];
    else         v = ((const float2*)(Wh + hcol * 128))[kp - 64];

    __half2 hv = __floats2half2_rn(v.x, v.y);
    *(uint32_t*)&g_wb[qh][(((ks * 8 + ntp) * 32 + lane) * 16) + e * 8 + j * 4] =
        *(uint32_t*)&hv;
}

// ============================================================================
// Kernel 2: persistent GEMM + LSTM epilogue. grid=296x256.
// blk&3 = qh (hcol quarter), blk>>2 strides batch tiles of 128 rows.
// Warp w: mgroup = w&3 (2 mtiles of 16 rows), g = w>>2 (ntp half).
// ============================================================================
__global__ void __launch_bounds__(256, 2)
lstm_main_kernel(
    const float* __restrict__ x, const float* __restrict__ h_t,
    const float* __restrict__ c_t,
    const float* __restrict__ b_i, const float* __restrict__ b_f,
    const float* __restrict__ b_g, const float* __restrict__ b_o,
    float* __restrict__ out, int batch, int mt_total)
{
    extern __shared__ char smem[];
    const uint32_t sb = smem_u32(smem);
    const uint32_t sW = sb + SMEM_W;
    float* bs = (float*)(smem + SMEM_BS);

    const int tid  = threadIdx.x;
    const int wid  = tid >> 5;
    const int lane = tid & 31;
    const int qh   = blockIdx.x & 3;
    const int cta  = blockIdx.x >> 2;          // 0..73
    const int mt_stride = gridDim.x >> 2;      // 74

    const int mgroup = wid & 3;
    const int g      = wid >> 2;

    // ---- load W fragments (once) via cp.async ----
    {
        const char* src = (const char*)&g_wb[qh][0] + tid * 16;
        uint32_t dst = sW + tid * 16;
        #pragma unroll
        for (int i = 0; i < 16; i++) {
            asm volatile("cp.async.ca.shared.global [%0], [%1], 16;\n"
                         :: "r"(dst + i * 4096), "l"(src + i * 4096));
        }
        asm volatile("cp.async.commit_group;\n" ::: "memory");
    }
    // ---- biases for this quarter: bs[q][hc] ----
    if (tid < 128) {
        int q  = tid >> 5;
        int hc = tid & 31;
        const float* bp = (q == 0) ? b_i : (q == 1) ? b_f : (q == 2) ? b_g : b_o;
        bs[tid] = bp[qh * 32 + hc];
    }
    asm volatile("cp.async.wait_group 0;\n" ::: "memory");
    __syncthreads();

    // per-thread A geometry: rows (rbase + m2*16) and +8, cols colq..colq+3
    const int rbase = (mgroup << 5) + (lane >> 2);
    const int colq  = (lane & 3) << 2;
    const size_t cbase = (size_t)batch * 128;

    // ---- persistent tile loop (NO __syncthreads inside) ----
    for (int mt = cta; mt < mt_total; mt += mt_stride) {

        float acc[2][4][2][4];                 // [m2][gate][e][frag]
        #pragma unroll
        for (int a0 = 0; a0 < 2; a0++)
            #pragma unroll
            for (int a1 = 0; a1 < 4; a1++)
                #pragma unroll
                for (int a2 = 0; a2 < 2; a2++)
                    #pragma unroll
                    for (int a3 = 0; a3 < 4; a3++)
                        acc[a0][a1][a2][a3] = 0.0f;

        const size_t rowoff = (size_t)(mt * 128 + rbase) * 128;

        float4 F[2][2];                        // [m2][row-half] staged fp32
        float4 Fn[2][2];

        // prologue: ks = 0 (from x)
        {
            const float* p0 = x + rowoff + colq;
            const float* p1 = p0 + (size_t)(16 * 128);
            F[0][0] = __ldg((const float4*)p0);
            F[0][1] = __ldg((const float4*)(p0 + 8 * 128));
            F[1][0] = __ldg((const float4*)p1);
            F[1][1] = __ldg((const float4*)(p1 + 8 * 128));
        }

        #pragma unroll 4
        for (int ks = 0; ks < 16; ks++) {
            // prefetch ks+1
            if (ks < 15) {
                const int ksn = ks + 1;
                const float* base = (ksn < 8) ? x : h_t;
                const int c = ((ksn & 7) << 4) + colq;
                const float* p0 = base + rowoff + c;
                const float* p1 = p0 + (size_t)(16 * 128);
                Fn[0][0] = __ldg((const float4*)p0);
                Fn[0][1] = __ldg((const float4*)(p0 + 8 * 128));
                Fn[1][0] = __ldg((const float4*)p1);
                Fn[1][1] = __ldg((const float4*)(p1 + 8 * 128));
            }

            // cvt staged fp32 -> A fragments (permuted k order, matches W pack)
            uint32_t afr[2][4];
            #pragma unroll
            for (int m2 = 0; m2 < 2; m2++) {
                afr[m2][0] = cvt_h2(F[m2][0].x, F[m2][0].y);   // row r,   k-lo
                afr[m2][1] = cvt_h2(F[m2][1].x, F[m2][1].y);   // row r+8, k-lo
                afr[m2][2] = cvt_h2(F[m2][0].z, F[m2][0].w);   // row r,   k-hi
                afr[m2][3] = cvt_h2(F[m2][1].z, F[m2][1].w);   // row r+8, k-hi
            }

            // B from smem: one LDS.128 per gate covers e=0 and e=1 fragments
            #pragma unroll
            for (int q = 0; q < 4; q++) {
                uint32_t baddr = sW + (((ks * 8 + q * 2 + g) * 32 + lane) * 16);
                uint32_t b0, b1, b2, b3;
                asm volatile("ld.shared.v4.b32 {%0,%1,%2,%3}, [%4];\n"
                             : "=r"(b0), "=r"(b1), "=r"(b2), "=r"(b3)
                             : "r"(baddr));
                mma16816(acc[0][q][0], afr[0], b0, b1);
                mma16816(acc[1][q][0], afr[1], b0, b1);
                mma16816(acc[0][q][1], afr[0], b2, b3);
                mma16816(acc[1][q][1], afr[1], b2, b3);
            }

            #pragma unroll
            for (int m2 = 0; m2 < 2; m2++) {
                F[m2][0] = Fn[m2][0];
                F[m2][1] = Fn[m2][1];
            }
        }

        // ---- epilogue ----
        #pragma unroll
        for (int m2 = 0; m2 < 2; m2++) {
            const int r0 = mt * 128 + (mgroup << 5) + (m2 << 4) + (lane >> 2);
            #pragma unroll
            for (int e = 0; e < 2; e++) {
                const int hc32 = (((g << 1) + e) << 3) + ((lane & 3) << 1);
                const int hcol = (qh << 5) + hc32;
                const float bi0 = bs[hc32],      bi1 = bs[hc32 + 1];
                const float bf0 = bs[32 + hc32], bf1 = bs[32 + hc32 + 1];
                const float bg0 = bs[64 + hc32], bg1 = bs[64 + hc32 + 1];
                const float bo0 = bs[96 + hc32], bo1 = bs[96 + hc32 + 1];
                #pragma unroll
                for (int rh = 0; rh < 2; rh++) {
                    const int row = r0 + rh * 8;
                    const float2 cv =
                        __ldg((const float2*)(c_t + (size_t)row * 128 + hcol));

                    float ia0 = acc[m2][0][e][rh * 2 + 0] + bi0;
                    float ia1 = acc[m2][0][e][rh * 2 + 1] + bi1;
                    float fa0 = acc[m2][1][e][rh * 2 + 0] + bf0;
                    float fa1 = acc[m2][1][e][rh * 2 + 1] + bf1;
                    float ga0 = acc[m2][2][e][rh * 2 + 0] + bg0;
                    float ga1 = acc[m2][2][e][rh * 2 + 1] + bg1;
                    float oa0 = acc[m2][3][e][rh * 2 + 0] + bo0;
                    float oa1 = acc[m2][3][e][rh * 2 + 1] + bo1;

                    float it0 = fast_sigmoid(ia0), it1 = fast_sigmoid(ia1);
                    float ft0 = fast_sigmoid(fa0), ft1 = fast_sigmoid(fa1);
                    float gt0 = fast_tanh(ga0),    gt1 = fast_tanh(ga1);
                    float ot0 = fast_sigmoid(oa0), ot1 = fast_sigmoid(oa1);

                    float cn0 = ft0 * cv.x + it0 * gt0;
                    float cn1 = ft1 * cv.y + it1 * gt1;
                    float hn0 = ot0 * fast_tanh(cn0);
                    float hn1 = ot1 * fast_tanh(cn1);

                    float2 ho = make_float2(hn0, hn1);
                    float2 co = make_float2(cn0, cn1);
                    *(float2*)(out + (size_t)row * 128 + hcol) = ho;
                    *(float2*)(out + cbase + (size_t)row * 128 + hcol) = co;
                }
            }
        }
        // no barrier needed: no shared A ring, W is read-only
    }
}

// ============================================================================
// Host launch
// ============================================================================
extern "C" void kernel_launch(void* const* d_in, const int* in_sizes, int n_in,
                              void* d_out, int out_size)
{
    (void)n_in; (void)out_size;
    const float* x   = (const float*)d_in[0];
    const float* h_t = (const float*)d_in[1];
    const float* c_t = (const float*)d_in[2];
    const float* Wii = (const float*)d_in[3];
    const float* Whi = (const float*)d_in[4];
    const float* b_i = (const float*)d_in[5];
    const float* Wif = (const float*)d_in[6];
    const float* Whf = (const float*)d_in[7];
    const float* b_f = (const float*)d_in[8];
    const float* Wig = (const float*)d_in[9];
    const float* Whg = (const float*)d_in[10];
    const float* b_g = (const float*)d_in[11];
    const float* Wio = (const float*)d_in[12];
    const float* Who = (const float*)d_in[13];
    const float* b_o = (const float*)d_in[14];

    const int batch    = in_sizes[0] / 128;
    const int mt_total = batch / 128;

    wconv_kernel<<<256, 256>>>(Wii, Whi, Wif, Whf, Wig, Whg, Wio, Who);

    static bool attr_set = false;
    if (!attr_set) {
        cudaFuncSetAttribute(lstm_main_kernel,
                             cudaFuncAttributeMaxDynamicSharedMemorySize,
                             SMEM_TOTAL);
        attr_set = true;
    }
    lstm_main_kernel<<<296, 256, SMEM_TOTAL>>>(
        x, h_t, c_t, b_i, b_f, b_g, b_o, (float*)d_out, batch, mt_total);
}

// round 8
// speedup vs baseline: 1.2593x; 1.0911x over previous
#include <cuda_runtime.h>
#include <cuda_fp16.h>
#include <cstdint>

// ============================================================================
// LSTMCell on GB300 via mma.sync (HMMA) — tcgen05 unavailable (compute_103 PTX).
// gates[B,512] = [x|h] @ Wcat^T, fp16 operands / fp32 accum, fused epilogue.
//
// R7 -> R8: A operand now goes through a 32KB smem ring:
//   fully-coalesced LDG.128 (thread = (row, kquad))  -> cvt fp32->fp16 ->
//   conflict-free STS.32 (uint-index XOR ks swizzle) -> one LDS.128 per
//   mtile-ks = full fragment (consumer un-permutes at compile time).
// A wavefronts: 4096 -> 2560 per CTA-tile. 4 barriers/tile (1 per 4-ks chunk).
// ============================================================================

// Weights pre-packed in mma-fragment-ready layout with k-permutation pi:
//   within each 16-wide k-chunk: frag j=0 holds k pairs (4l,4l+1), j=1 (4l+2,4l+3)
// addr = (((ks*8 + ntp)*32 + lane)*16) + e*8 + j*4
__device__ __align__(16) unsigned char g_wb[4][65536];

__device__ __forceinline__ uint32_t smem_u32(const void* p) {
    uint32_t a;
    asm("{ .reg .u64 t; cvta.to.shared.u64 t, %1; cvt.u32.u64 %0, t; }"
        : "=r"(a) : "l"(p));
    return a;
}

__device__ __forceinline__ float fast_sigmoid(float x) {
    float e, r;
    asm("ex2.approx.f32 %0, %1;" : "=f"(e) : "f"(-1.4426950408889634f * x));
    asm("rcp.approx.f32 %0, %1;" : "=f"(r) : "f"(1.0f + e));
    return r;
}
__device__ __forceinline__ float fast_tanh(float x) {
    float e, r;
    asm("ex2.approx.f32 %0, %1;" : "=f"(e) : "f"(2.8853900817779268f * x));
    asm("rcp.approx.f32 %0, %1;" : "=f"(r) : "f"(e + 1.0f));
    return 1.0f - 2.0f * r;   // handles +-inf correctly -> +-1
}

__device__ __forceinline__ uint32_t cvt_h2(float lo, float hi) {
    uint32_t r;
    asm("cvt.rn.f16x2.f32 %0, %1, %2;" : "=r"(r) : "f"(hi), "f"(lo));
    return r;
}

__device__ __forceinline__ void mma16816(float* d, const uint32_t* a,
                                         uint32_t b0, uint32_t b1) {
    asm volatile(
        "mma.sync.aligned.m16n8k16.row.col.f32.f16.f16.f32 "
        "{%0,%1,%2,%3}, {%4,%5,%6,%7}, {%8,%9}, {%0,%1,%2,%3};\n"
        : "+f"(d[0]), "+f"(d[1]), "+f"(d[2]), "+f"(d[3])
        : "r"(a[0]), "r"(a[1]), "r"(a[2]), "r"(a[3]), "r"(b0), "r"(b1));
}

__device__ __forceinline__ void lds128(uint32_t* r, uint32_t addr) {
    asm volatile("ld.shared.v4.b32 {%0,%1,%2,%3}, [%4];\n"
                 : "=r"(r[0]), "=r"(r[1]), "=r"(r[2]), "=r"(r[3]) : "r"(addr));
}
__device__ __forceinline__ void sts32(uint32_t addr, uint32_t v) {
    asm volatile("st.shared.b32 [%0], %1;\n" :: "r"(addr), "r"(v));
}

// ---------------- SMEM layout (dynamic) ----------------
// [0, 65536)        : W fragments
// [65536, 98304)    : A ring, 2 slots x 16KB (slot: [ks(4)][mt(8)][lane(32)][16B])
// [98304, 98816)    : bias bs[4][32]
static constexpr int SMEM_W  = 0;
static constexpr int SMEM_A  = 65536;
static constexpr int SMEM_BS = 98304;
static constexpr int SMEM_TOTAL = SMEM_BS + 512;

// ============================================================================
// Kernel 1: pack weights fp32 -> fp16 B-fragment layout (with k-permutation).
// ============================================================================
__global__ void wconv_kernel(
    const float* __restrict__ Wii, const float* __restrict__ Whi,
    const float* __restrict__ Wif, const float* __restrict__ Whf,
    const float* __restrict__ Wig, const float* __restrict__ Whg,
    const float* __restrict__ Wio, const float* __restrict__ Who)
{
    int idx = blockIdx.x * 256 + threadIdx.x;   // 0..65535 (pairs)
    int gcol = idx >> 7;        // 0..511
    int kp   = idx & 127;       // pair index, k = 2*kp
    int k    = kp * 2;

    int q    = gcol >> 7;
    int hcol = gcol & 127;
    int qh   = hcol >> 5;
    int hc   = hcol & 31;

    int t    = hc >> 3;                 // 8-col group within 32
    int ntp  = q * 2 + (t >> 1);
    int e    = t & 1;
    int l    = (k >> 2) & 3;
    int j    = (k >> 1) & 1;
    int lane = (hc & 7) * 4 + l;
    int ks   = k >> 4;

    const float* Wx;
    const float* Wh;
    switch (q) {
        case 0:  Wx = Wii; Wh = Whi; break;
        case 1:  Wx = Wif; Wh = Whf; break;
        case 2:  Wx = Wig; Wh = Whg; break;
        default: Wx = Wio; Wh = Who; break;
    }
    float2 v;
    if (k < 128) v = ((const float2*)(Wx + hcol * 128))[kp];
    else         v = ((const float2*)(Wh + hcol * 128))[kp - 64];

    __half2 hv = __floats2half2_rn(v.x, v.y);
    *(uint32_t*)&g_wb[qh][(((ks * 8 + ntp) * 32 + lane) * 16) + e * 8 + j * 4] =
        *(uint32_t*)&hv;
}

// ============================================================================
// Kernel 2: persistent GEMM + LSTM epilogue. grid=296x256.
// blk&3 = qh (hcol quarter), blk>>2 strides batch tiles of 128 rows.
// Warp w: mgroup = w&3 (mtiles 2*mgroup, 2*mgroup+1), g = w>>2 (ntp half).
// ============================================================================
__global__ void __launch_bounds__(256, 2)
lstm_main_kernel(
    const float* __restrict__ x, const float* __restrict__ h_t,
    const float* __restrict__ c_t,
    const float* __restrict__ b_i, const float* __restrict__ b_f,
    const float* __restrict__ b_g, const float* __restrict__ b_o,
    float* __restrict__ out, int batch, int mt_total)
{
    extern __shared__ char smem[];
    const uint32_t sb = smem_u32(smem);
    const uint32_t sW = sb + SMEM_W;
    const uint32_t sA = sb + SMEM_A;
    float* bs = (float*)(smem + SMEM_BS);

    const int tid  = threadIdx.x;
    const int wid  = tid >> 5;
    const int lane = tid & 31;
    const int qh   = blockIdx.x & 3;
    const int cta  = blockIdx.x >> 2;          // 0..73
    const int mt_stride = gridDim.x >> 2;      // 74

    const int mgroup = wid & 3;
    const int g      = wid >> 2;

    // ---- load W fragments (once) via cp.async ----
    {
        const char* src = (const char*)&g_wb[qh][0] + tid * 16;
        uint32_t dst = sW + tid * 16;
        #pragma unroll
        for (int i = 0; i < 16; i++) {
            asm volatile("cp.async.ca.shared.global [%0], [%1], 16;\n"
                         :: "r"(dst + i * 4096), "l"(src + i * 4096));
        }
        asm volatile("cp.async.commit_group;\n" ::: "memory");
    }
    // ---- biases for this quarter: bs[q][hc] ----
    if (tid < 128) {
        int q  = tid >> 5;
        int hc = tid & 31;
        const float* bp = (q == 0) ? b_i : (q == 1) ? b_f : (q == 2) ? b_g : b_o;
        bs[tid] = bp[qh * 32 + hc];
    }
    asm volatile("cp.async.wait_group 0;\n" ::: "memory");
    __syncthreads();

    // ---- producer geometry: thread = (r0 = tid>>4 in 0..15, kq = tid&15) ----
    const int r0   = tid >> 4;                 // row within 16-row i-slab
    const int kq   = tid & 15;                 // k-quad within 64-k chunk
    const int ksIn = kq >> 2;                  // ks within chunk (0..3)
    const int lq   = kq & 3;                   // k-pair group l
    const int c8   = r0 & 7;
    const int hh   = r0 >> 3;
    // smem dest offsets (bytes), per i add 512 (mt stride):
    const uint32_t duBase = (uint32_t)(ksIn * 4096 + (c8 * 4 + lq) * 16);
    const uint32_t d0u = duBase + (uint32_t)(((hh)     ^ ksIn) * 4);  // j=0
    const uint32_t d1u = duBase + (uint32_t)(((hh + 2) ^ ksIn) * 4);  // j=1
    // gmem source offset within a chunk's base (floats):
    const int thOff = r0 * 128 + ksIn * 16 + lq * 4;

    // ---- consumer geometry ----
    const uint32_t aLane = (uint32_t)(mgroup * 1024 + lane * 16);
    const uint32_t bLane = sW + (uint32_t)(g * 512 + lane * 16);
    const size_t cbase = (size_t)batch * 128;

    // ---- persistent tile loop ----
    for (int mt = cta; mt < mt_total; mt += mt_stride) {

        float acc[2][4][2][4];                 // [m2][gate][e][frag]
        #pragma unroll
        for (int a0 = 0; a0 < 2; a0++)
            #pragma unroll
            for (int a1 = 0; a1 < 4; a1++)
                #pragma unroll
                for (int a2 = 0; a2 < 2; a2++)
                    #pragma unroll
                    for (int a3 = 0; a3 < 4; a3++)
                        acc[a0][a1][a2][a3] = 0.0f;

        // chunk base pointers (thread-offset included)
        const size_t tilebase = (size_t)(mt * 128) * 128 + thOff;
        const float* bp[4] = { x + tilebase,       x + tilebase + 64,
                               h_t + tilebase,     h_t + tilebase + 64 };

        float4 F[8];

        // ---- prologue: chunk 0 -> slot 0 ----
        #pragma unroll
        for (int i = 0; i < 8; i++)
            F[i] = __ldg((const float4*)(bp[0] + i * 2048));
        {
            uint32_t ds = sA + 0;
            #pragma unroll
            for (int i = 0; i < 8; i++) {
                uint32_t j0 = cvt_h2(F[i].x, F[i].y);
                uint32_t j1 = cvt_h2(F[i].z, F[i].w);
                sts32(ds + (uint32_t)(i * 512) + d0u, j0);
                sts32(ds + (uint32_t)(i * 512) + d1u, j1);
            }
        }
        __syncthreads();

        // ---- chunk loop ----
        #pragma unroll
        for (int c = 0; c < 4; c++) {
            // prefetch chunk c+1 (gmem -> regs); latency hidden by mma below
            if (c < 3) {
                const float* p = bp[c + 1];
                #pragma unroll
                for (int i = 0; i < 8; i++)
                    F[i] = __ldg((const float4*)(p + i * 2048));
            }

            // consume chunk c from slot c&1
            {
                const uint32_t as = sA + (uint32_t)((c & 1) * 16384) + aLane;
                const uint32_t bb0 = bLane + (uint32_t)(c * 16384);
                #pragma unroll
                for (int ks = 0; ks < 4; ks++) {
                    uint32_t A0[4], A1[4];
                    lds128(A0, as + (uint32_t)(ks * 4096));
                    lds128(A1, as + (uint32_t)(ks * 4096 + 512));
                    uint32_t a0p[4] = { A0[0 ^ ks], A0[1 ^ ks], A0[2 ^ ks], A0[3 ^ ks] };
                    uint32_t a1p[4] = { A1[0 ^ ks], A1[1 ^ ks], A1[2 ^ ks], A1[3 ^ ks] };
                    const uint32_t bb = bb0 + (uint32_t)(ks * 4096);
                    #pragma unroll
                    for (int q = 0; q < 4; q++) {
                        uint32_t B[4];
                        lds128(B, bb + (uint32_t)(q * 1024));
                        mma16816(acc[0][q][0], a0p, B[0], B[1]);
                        mma16816(acc[1][q][0], a1p, B[0], B[1]);
                        mma16816(acc[0][q][1], a0p, B[2], B[3]);
                        mma16816(acc[1][q][1], a1p, B[2], B[3]);
                    }
                }
            }

            // convert + store chunk c+1 into slot (c+1)&1
            if (c < 3) {
                uint32_t ds = sA + (uint32_t)(((c + 1) & 1) * 16384);
                #pragma unroll
                for (int i = 0; i < 8; i++) {
                    uint32_t j0 = cvt_h2(F[i].x, F[i].y);
                    uint32_t j1 = cvt_h2(F[i].z, F[i].w);
                    sts32(ds + (uint32_t)(i * 512) + d0u, j0);
                    sts32(ds + (uint32_t)(i * 512) + d1u, j1);
                }
                __syncthreads();
            }
        }
        // note: no barrier after chunk 3 consume — next write to slot0 is the
        // next tile's prologue STS, and all slot0 consumers finished before the
        // barrier at end of chunk-2 iteration; slot1 consumers (chunk 3) finish
        // before the barrier after the next tile's prologue STS.

        // ---- epilogue ----
        #pragma unroll
        for (int m2 = 0; m2 < 2; m2++) {
            const int rr0 = mt * 128 + (mgroup << 5) + (m2 << 4) + (lane >> 2);
            #pragma unroll
            for (int e = 0; e < 2; e++) {
                const int hc32 = (((g << 1) + e) << 3) + ((lane & 3) << 1);
                const int hcol = (qh << 5) + hc32;
                const float bi0 = bs[hc32],      bi1 = bs[hc32 + 1];
                const float bf0 = bs[32 + hc32], bf1 = bs[32 + hc32 + 1];
                const float bg0 = bs[64 + hc32], bg1 = bs[64 + hc32 + 1];
                const float bo0 = bs[96 + hc32], bo1 = bs[96 + hc32 + 1];
                #pragma unroll
                for (int rh = 0; rh < 2; rh++) {
                    const int row = rr0 + rh * 8;
                    const float2 cv =
                        __ldg((const float2*)(c_t + (size_t)row * 128 + hcol));

                    float ia0 = acc[m2][0][e][rh * 2 + 0] + bi0;
                    float ia1 = acc[m2][0][e][rh * 2 + 1] + bi1;
                    float fa0 = acc[m2][1][e][rh * 2 + 0] + bf0;
                    float fa1 = acc[m2][1][e][rh * 2 + 1] + bf1;
                    float ga0 = acc[m2][2][e][rh * 2 + 0] + bg0;
                    float ga1 = acc[m2][2][e][rh * 2 + 1] + bg1;
                    float oa0 = acc[m2][3][e][rh * 2 + 0] + bo0;
                    float oa1 = acc[m2][3][e][rh * 2 + 1] + bo1;

                    float it0 = fast_sigmoid(ia0), it1 = fast_sigmoid(ia1);
                    float ft0 = fast_sigmoid(fa0), ft1 = fast_sigmoid(fa1);
                    float gt0 = fast_tanh(ga0),    gt1 = fast_tanh(ga1);
                    float ot0 = fast_sigmoid(oa0), ot1 = fast_sigmoid(oa1);

                    float cn0 = ft0 * cv.x + it0 * gt0;
                    float cn1 = ft1 * cv.y + it1 * gt1;
                    float hn0 = ot0 * fast_tanh(cn0);
                    float hn1 = ot1 * fast_tanh(cn1);

                    float2 ho = make_float2(hn0, hn1);
                    float2 co = make_float2(cn0, cn1);
                    *(float2*)(out + (size_t)row * 128 + hcol) = ho;
                    *(float2*)(out + cbase + (size_t)row * 128 + hcol) = co;
                }
            }
        }
    }
}

// ============================================================================
// Host launch
// ============================================================================
extern "C" void kernel_launch(void* const* d_in, const int* in_sizes, int n_in,
                              void* d_out, int out_size)
{
    (void)n_in; (void)out_size;
    const float* x   = (const float*)d_in[0];
    const float* h_t = (const float*)d_in[1];
    const float* c_t = (const float*)d_in[2];
    const float* Wii = (const float*)d_in[3];
    const float* Whi = (const float*)d_in[4];
    const float* b_i = (const float*)d_in[5];
    const float* Wif = (const float*)d_in[6];
    const float* Whf = (const float*)d_in[7];
    const float* b_f = (const float*)d_in[8];
    const float* Wig = (const float*)d_in[9];
    const float* Whg = (const float*)d_in[10];
    const float* b_g = (const float*)d_in[11];
    const float* Wio = (const float*)d_in[12];
    const float* Who = (const float*)d_in[13];
    const float* b_o = (const float*)d_in[14];

    const int batch    = in_sizes[0] / 128;
    const int mt_total = batch / 128;

    wconv_kernel<<<256, 256>>>(Wii, Whi, Wif, Whf, Wig, Whg, Wio, Who);

    static bool attr_set = false;
    if (!attr_set) {
        cudaFuncSetAttribute(lstm_main_kernel,
                             cudaFuncAttributeMaxDynamicSharedMemorySize,
                             SMEM_TOTAL);
        attr_set = true;
    }
    lstm_main_kernel<<<296, 256, SMEM_TOTAL>>>(
        x, h_t, c_t, b_i, b_f, b_g, b_o, (float*)d_out, batch, mt_total);
}